// round 7
// baseline (speedup 1.0000x reference)
#include <cuda_runtime.h>
#include <cstdint>
#include <math.h>

#define T_STEPS 256
#define BATCH   64
#define HID     256
#define G3      768           // 3*HID
#define VOCAB   5000
#define RK_PAD  260           // 256 + 4 floats pad -> conflict-free, 16B-aligned rows

// Scratch (static __device__ arrays: allowed; no runtime allocation)
__device__ float g_MX[(size_t)T_STEPS * BATCH * G3];   // [t][b][3H], includes b_in
__device__ float g_Y [(size_t)T_STEPS * BATCH * HID];  // [t][b][H]

// ---------------------------------------------------------------------------
// Kernel 1: MX[t][b][n] = kernel[tokens[b][t]][n] + b_in[n]   (gather)
// ---------------------------------------------------------------------------
__global__ void mx_kernel(const int* __restrict__ tokens,
                          const float* __restrict__ Wk,
                          const float* __restrict__ bias) {
    int idx = blockIdx.x * 256 + threadIdx.x;       // exactly T*B*G3 threads
    int n  = idx % G3;
    int tb = idx / G3;
    int b  = tb % BATCH;
    int t  = tb / BATCH;
    int tok = tokens[b * T_STEPS + t];
    g_MX[idx] = Wk[(size_t)tok * G3 + n] + bias[n];
}

// ---------------------------------------------------------------------------
// Kernel 2 (primary): GRU scan. 32 clusters x 4 CTAs, 64 thr/CTA, 2 seq/cluster.
// CTA rank r holds rkernel fp32 slice for hidden cols j in [r*64, r*64+64)
// i.e. global cols {j, 256+j, 512+j}, stored transposed [n_local][k] in SMEM.
// Thread jj owns hidden col j = r*64+jj: computes all 3 gates for both seqs.
// h exchanged cluster-wide via DSMEM stores + cluster barrier each step.
// ---------------------------------------------------------------------------
__device__ __forceinline__ uint32_t smem_u32(const void* p) {
    uint32_t a;
    asm("{ .reg .u64 t; cvta.to.shared.u64 t, %1; cvt.u32.u64 %0, t; }"
        : "=r"(a) : "l"(p));
    return a;
}
__device__ __forceinline__ void st_cluster_f32(uint32_t laddr, int rank, float v) {
    uint32_t ra;
    asm volatile("mapa.shared::cluster.u32 %0, %1, %2;" : "=r"(ra) : "r"(laddr), "r"(rank));
    asm volatile("st.shared::cluster.f32 [%0], %1;" :: "r"(ra), "f"(v) : "memory");
}
__device__ __forceinline__ void cluster_sync_() {
    asm volatile("barrier.cluster.arrive.aligned;" ::: "memory");
    asm volatile("barrier.cluster.wait.aligned;"   ::: "memory");
}
__device__ __forceinline__ float sigmoidf_(float x) { return 1.0f / (1.0f + expf(-x)); }

__global__ void __cluster_dims__(4, 1, 1) scan_kernel(
    const float* __restrict__ h0,
    const float* __restrict__ rkernel,
    const float* __restrict__ bias,
    float* __restrict__ out, int write_hlast)
{
    extern __shared__ float sm[];
    float* rk = sm;                       // [192][RK_PAD]
    float* hb = sm + 192 * RK_PAD;        // [2 parity][2 seq][HID]
    const int tid = threadIdx.x;          // 0..63
    uint32_t crank;
    asm("mov.u32 %0, %%cluster_ctarank;" : "=r"(crank));
    const int cid  = blockIdx.x >> 2;
    const int seq0 = cid * 2;

    // Load rkernel slice (transpose to [n_local][k]); one-time.
    for (int e = tid; e < 192 * HID; e += 64) {
        int nl  = e % 192;
        int k   = e / 192;
        int col = (nl >> 6) * HID + (int)crank * 64 + (nl & 63);
        rk[nl * RK_PAD + k] = rkernel[(size_t)k * G3 + col];
    }
    // Load h0 for our two sequences into parity-0 buffer.
    for (int e = tid; e < 2 * HID; e += 64) {
        int s = e >> 8, k = e & 255;
        hb[s * HID + k] = h0[(size_t)(seq0 + s) * HID + k];
    }
    const int j = (int)crank * 64 + tid;          // my hidden column
    const float brz = bias[G3 + j];
    const float brr = bias[G3 + HID + j];
    const float brh = bias[G3 + 2 * HID + j];
    __syncthreads();
    cluster_sync_();

    const float* w0 = rk + (size_t)tid * RK_PAD;          // gate z row
    const float* w1 = rk + (size_t)(64  + tid) * RK_PAD;  // gate r row
    const float* w2 = rk + (size_t)(128 + tid) * RK_PAD;  // gate h row
    const uint32_t hb_addr = smem_u32(hb);

    for (int t = 0; t < T_STEPS; ++t) {
        const int cur = t & 1, nxt = cur ^ 1;
        // Prefetch MX for this step (consumed only in epilogue -> latency hidden)
        const float* mxp = g_MX + ((size_t)t * BATCH + seq0) * G3 + j;
        float mxz0 = mxp[0],   mxr0 = mxp[HID],      mxh0 = mxp[2 * HID];
        float mxz1 = mxp[G3],  mxr1 = mxp[G3 + HID], mxh1 = mxp[G3 + 2 * HID];

        const float* hc0 = hb + cur * (2 * HID);
        const float* hc1 = hc0 + HID;
        float az0 = 0.f, ar0 = 0.f, ah0 = 0.f;
        float az1 = 0.f, ar1 = 0.f, ah1 = 0.f;
        #pragma unroll 4
        for (int k = 0; k < HID; k += 4) {
            float4 wz = *reinterpret_cast<const float4*>(w0 + k);
            float4 wr = *reinterpret_cast<const float4*>(w1 + k);
            float4 wh = *reinterpret_cast<const float4*>(w2 + k);
            float4 ha = *reinterpret_cast<const float4*>(hc0 + k);  // broadcast
            float4 hv = *reinterpret_cast<const float4*>(hc1 + k);  // broadcast
            az0 = fmaf(wz.x, ha.x, az0); az0 = fmaf(wz.y, ha.y, az0);
            az0 = fmaf(wz.z, ha.z, az0); az0 = fmaf(wz.w, ha.w, az0);
            ar0 = fmaf(wr.x, ha.x, ar0); ar0 = fmaf(wr.y, ha.y, ar0);
            ar0 = fmaf(wr.z, ha.z, ar0); ar0 = fmaf(wr.w, ha.w, ar0);
            ah0 = fmaf(wh.x, ha.x, ah0); ah0 = fmaf(wh.y, ha.y, ah0);
            ah0 = fmaf(wh.z, ha.z, ah0); ah0 = fmaf(wh.w, ha.w, ah0);
            az1 = fmaf(wz.x, hv.x, az1); az1 = fmaf(wz.y, hv.y, az1);
            az1 = fmaf(wz.z, hv.z, az1); az1 = fmaf(wz.w, hv.w, az1);
            ar1 = fmaf(wr.x, hv.x, ar1); ar1 = fmaf(wr.y, hv.y, ar1);
            ar1 = fmaf(wr.z, hv.z, ar1); ar1 = fmaf(wr.w, hv.w, ar1);
            ah1 = fmaf(wh.x, hv.x, ah1); ah1 = fmaf(wh.y, hv.y, ah1);
            ah1 = fmaf(wh.z, hv.z, ah1); ah1 = fmaf(wh.w, hv.w, ah1);
        }
        // Gates (reset_after=True): cand = tanh(xh + r*(hh + b_rec_h))
        float z0 = sigmoidf_(mxz0 + az0 + brz);
        float r0 = sigmoidf_(mxr0 + ar0 + brr);
        float c0 = tanhf(mxh0 + r0 * (ah0 + brh));
        float hp0 = hc0[j];
        float hn0 = z0 * hp0 + (1.0f - z0) * c0;

        float z1 = sigmoidf_(mxz1 + az1 + brz);
        float r1 = sigmoidf_(mxr1 + ar1 + brr);
        float c1 = tanhf(mxh1 + r1 * (ah1 + brh));
        float hp1 = hc1[j];
        float hn1 = z1 * hp1 + (1.0f - z1) * c1;

        g_Y[((size_t)t * BATCH + seq0) * HID + j]     = hn0;
        g_Y[((size_t)t * BATCH + seq0 + 1) * HID + j] = hn1;

        // Broadcast h_new slice into every CTA's next-parity buffer
        uint32_t a0 = hb_addr + (uint32_t)((nxt * 2 * HID + j) * 4);
        uint32_t a1 = a0 + HID * 4;
        #pragma unroll
        for (int rc = 0; rc < 4; ++rc) {
            st_cluster_f32(a0, rc, hn0);
            st_cluster_f32(a1, rc, hn1);
        }
        if (write_hlast && t == T_STEPS - 1) {
            size_t hl = (size_t)VOCAB * (T_STEPS * BATCH);
            out[hl + (size_t)seq0 * HID + j]       = hn0;
            out[hl + (size_t)(seq0 + 1) * HID + j] = hn1;
        }
        cluster_sync_();   // release remote stores / start next step
    }
}

// ---------------------------------------------------------------------------
// Kernel 2 (fallback, no clusters, no opt-in smem): 64 CTAs, one per sequence,
// 256 threads; rkernel read from L2 each step. Slower but hazard-free.
// Only used if the large-smem attribute set fails.
// ---------------------------------------------------------------------------
__global__ void __launch_bounds__(256) scan_fallback(
    const float* __restrict__ h0,
    const float* __restrict__ rkernel,
    const float* __restrict__ bias,
    float* __restrict__ out, int write_hlast)
{
    __shared__ float hcur[HID];
    const int b = blockIdx.x;
    const int tid = threadIdx.x;          // owns hidden col tid
    hcur[tid] = h0[(size_t)b * HID + tid];
    const float brz = bias[G3 + tid];
    const float brr = bias[G3 + HID + tid];
    const float brh = bias[G3 + 2 * HID + tid];
    __syncthreads();

    for (int t = 0; t < T_STEPS; ++t) {
        const float* mxp = g_MX + ((size_t)t * BATCH + b) * G3 + tid;
        float mxz = mxp[0], mxr = mxp[HID], mxh = mxp[2 * HID];
        float az = 0.f, ar = 0.f, ah = 0.f;
        #pragma unroll 8
        for (int k = 0; k < HID; ++k) {
            float hk = hcur[k];
            const float* rrow = rkernel + (size_t)k * G3;
            az = fmaf(rrow[tid],           hk, az);
            ar = fmaf(rrow[HID + tid],     hk, ar);
            ah = fmaf(rrow[2 * HID + tid], hk, ah);
        }
        float z = sigmoidf_(mxz + az + brz);
        float r = sigmoidf_(mxr + ar + brr);
        float c = tanhf(mxh + r * (ah + brh));
        float hp = hcur[tid];
        float hn = z * hp + (1.0f - z) * c;
        __syncthreads();
        hcur[tid] = hn;
        g_Y[((size_t)t * BATCH + b) * HID + tid] = hn;
        if (write_hlast && t == T_STEPS - 1)
            out[(size_t)VOCAB * (T_STEPS * BATCH) + (size_t)b * HID + tid] = hn;
        __syncthreads();
    }
}

// ---------------------------------------------------------------------------
// Kernel 3: out = Y[16384,256] @ Wd[256,5000] + bd, tf32 mma.sync (m16n8k8)
// 128x128 tiles, BK=32, 8 warps (2x4), warp tile 64x32.
// ---------------------------------------------------------------------------
__device__ __forceinline__ uint32_t f2tf(float f) {
    uint32_t u;
    asm("cvt.rna.tf32.f32 %0, %1;" : "=r"(u) : "f"(f));
    return u;
}
__device__ __forceinline__ void mma_tf32(float d[4], const uint32_t a[4], const uint32_t b[2]) {
    asm volatile(
        "mma.sync.aligned.m16n8k8.row.col.f32.tf32.tf32.f32 "
        "{%0,%1,%2,%3}, {%4,%5,%6,%7}, {%8,%9}, {%0,%1,%2,%3};\n"
        : "+f"(d[0]), "+f"(d[1]), "+f"(d[2]), "+f"(d[3])
        : "r"(a[0]), "r"(a[1]), "r"(a[2]), "r"(a[3]), "r"(b[0]), "r"(b[1]));
}

__global__ void __launch_bounds__(256) proj_kernel(
    const float* __restrict__ Wd, const float* __restrict__ bd,
    float* __restrict__ out)
{
    __shared__ uint32_t As[128 * 33];   // [row][k], stride 33
    __shared__ uint32_t Bs[32 * 132];   // [k][col], stride 132
    const int tid  = threadIdx.x;
    const int lane = tid & 31, wid = tid >> 5;
    const int wr = wid >> 2, wc = wid & 3;       // warp grid 2x4
    const int n0 = blockIdx.x * 128;
    const int i0 = blockIdx.y * 128;

    float acc[4][4][4];
    #pragma unroll
    for (int mi = 0; mi < 4; mi++)
        #pragma unroll
        for (int ni = 0; ni < 4; ni++)
            #pragma unroll
            for (int q = 0; q < 4; q++) acc[mi][ni][q] = 0.0f;

    for (int k0 = 0; k0 < HID; k0 += 32) {
        // A: Y tile 128x32
        for (int e = tid; e < 1024; e += 256) {
            int row = e >> 3;
            int c4  = (e & 7) << 2;
            float4 v = *reinterpret_cast<const float4*>(
                &g_Y[(size_t)(i0 + row) * HID + k0 + c4]);
            As[row * 33 + c4 + 0] = f2tf(v.x);
            As[row * 33 + c4 + 1] = f2tf(v.y);
            As[row * 33 + c4 + 2] = f2tf(v.z);
            As[row * 33 + c4 + 3] = f2tf(v.w);
        }
        // B: Wd tile 32x128 (zero-fill past VOCAB)
        for (int e = tid; e < 1024; e += 256) {
            int row = e >> 5;
            int c4  = (e & 31) << 2;
            int col = n0 + c4;
            float4 v = make_float4(0.f, 0.f, 0.f, 0.f);
            if (col < VOCAB)
                v = *reinterpret_cast<const float4*>(
                    &Wd[(size_t)(k0 + row) * VOCAB + col]);
            Bs[row * 132 + c4 + 0] = f2tf(v.x);
            Bs[row * 132 + c4 + 1] = f2tf(v.y);
            Bs[row * 132 + c4 + 2] = f2tf(v.z);
            Bs[row * 132 + c4 + 3] = f2tf(v.w);
        }
        __syncthreads();
        #pragma unroll
        for (int kk = 0; kk < 32; kk += 8) {
            uint32_t a[4][4], b[4][2];
            #pragma unroll
            for (int mi = 0; mi < 4; mi++) {
                int ar = wr * 64 + mi * 16 + (lane >> 2);
                int ac = kk + (lane & 3);
                a[mi][0] = As[ar * 33 + ac];
                a[mi][1] = As[(ar + 8) * 33 + ac];
                a[mi][2] = As[ar * 33 + ac + 4];
                a[mi][3] = As[(ar + 8) * 33 + ac + 4];
            }
            #pragma unroll
            for (int ni = 0; ni < 4; ni++) {
                int bc = wc * 32 + ni * 8 + (lane >> 2);
                int br = kk + (lane & 3);
                b[ni][0] = Bs[br * 132 + bc];
                b[ni][1] = Bs[(br + 4) * 132 + bc];
            }
            #pragma unroll
            for (int mi = 0; mi < 4; mi++)
                #pragma unroll
                for (int ni = 0; ni < 4; ni++)
                    mma_tf32(acc[mi][ni], a[mi], b[ni]);
        }
        __syncthreads();
    }
    // Epilogue: + bd, store
    #pragma unroll
    for (int mi = 0; mi < 4; mi++) {
        int r0 = i0 + wr * 64 + mi * 16 + (lane >> 2);
        #pragma unroll
        for (int ni = 0; ni < 4; ni++) {
            int cb = n0 + wc * 32 + ni * 8 + ((lane & 3) << 1);
            if (cb < VOCAB) {     // VOCAB even, cb even -> covers cb+1 too
                float b0v = bd[cb], b1v = bd[cb + 1];
                out[(size_t)r0 * VOCAB + cb]           = acc[mi][ni][0] + b0v;
                out[(size_t)r0 * VOCAB + cb + 1]       = acc[mi][ni][1] + b1v;
                out[(size_t)(r0 + 8) * VOCAB + cb]     = acc[mi][ni][2] + b0v;
                out[(size_t)(r0 + 8) * VOCAB + cb + 1] = acc[mi][ni][3] + b1v;
            }
        }
    }
}

// ---------------------------------------------------------------------------
// kernel_launch: mx gather -> clustered scan (or fallback) -> tf32 projection
// Inputs (metadata order): tokens, h0, kernel, rkernel, bias, Wd, bd
// ---------------------------------------------------------------------------
extern "C" void kernel_launch(void* const* d_in, const int* in_sizes, int n_in,
                              void* d_out, int out_size) {
    const int*   tokens = (const int*)  d_in[0];
    const float* h0     = (const float*)d_in[1];
    const float* Wk     = (const float*)d_in[2];
    const float* rker   = (const float*)d_in[3];
    const float* bias   = (const float*)d_in[4];
    const float* Wd     = (const float*)d_in[5];
    const float* bd     = (const float*)d_in[6];
    float* out = (float*)d_out;

    const long hl_need = (long)VOCAB * T_STEPS * BATCH + (long)BATCH * HID;
    int write_hl = ((long)out_size >= hl_need) ? 1 : 0;

    size_t scan_smem = (size_t)(192 * RK_PAD + 2 * 2 * HID) * sizeof(float); // 203,776 B
    cudaError_t attr_ok = cudaFuncSetAttribute(
        scan_kernel, cudaFuncAttributeMaxDynamicSharedMemorySize, (int)scan_smem);

    // 1) embed gather: T*B*G3 / 256 = 49152 blocks
    mx_kernel<<<(T_STEPS * BATCH * G3) / 256, 256>>>(tokens, Wk, bias);

    // 2) scan
    if (attr_ok == cudaSuccess) {
        scan_kernel<<<128, 64, scan_smem>>>(h0, rker, bias, out, write_hl);
    } else {
        scan_fallback<<<BATCH, HID>>>(h0, rker, bias, out, write_hl);
    }

    // 3) projection: 40 x 128 tiles of 128x128
    proj_kernel<<<dim3((VOCAB + 127) / 128, (T_STEPS * BATCH) / 128), 256>>>(Wd, bd, out);
}